// round 16
// baseline (speedup 1.0000x reference)
#include <cuda_runtime.h>
#include <cuda_fp16.h>
#include <cstdint>
#include <cstddef>

#define HH 128
#define WW 128
#define HW 16384
#define BB 4

// ---------------- scratch (static device globals; no allocation) ----------------
__device__ __half   g_multi[(size_t)BB * 768 * HW];   // qkv (0..383) + ms (384..767), planar
__device__ __half   g_msdw[(size_t)BB * 384 * HW];    // depthwise 5x5 output, planar
__device__ uint32_t g_atti[(size_t)BB * 128 * HW];    // attention output, half2 pairs
__device__ float    g_attended[(size_t)BB * 128 * HW];// residual branch point (fp32)
__device__ __half   g_h1[(size_t)BB * 768 * HW];      // mb1 output, planar
__device__ uint32_t g_h2i[(size_t)BB * 384 * HW];     // mb2 output, half2 pairs
__device__ float    g_kv[(size_t)BB * 32 * 2 * 72];   // per-(b,g,chunk) partial kv
__device__ float    g_wT[768 * 1152];                 // fragment-packed fp16 weights (uint4 view)
__device__ uint32_t g_refi[(size_t)BB * 64 * HW];     // ref as half2 channel pairs
__device__ uint32_t g_othi[(size_t)BB * 64 * HW];     // oth as half2 channel pairs

// fragment-region offsets in uint4 units
#define FQ 0
#define FK 18432
#define FV 36864
#define FP 55296
#define F1 59392
#define F3 71680

// conv dynamic smem: Afrag [2][2304] uint4 + Ish [2][8*3*136] uint32
#define CONV_SMEM (2 * 2304 * 16 + 2 * 3264 * 4)

// ---------------- fp16 mma helpers ----------------
__device__ __forceinline__ uint32_t packh2(float a, float b) {
    __half2 h = __floats2half2_rn(a, b);
    return *(uint32_t*)&h;
}

__device__ __forceinline__ void mma_fp16(float& d0, float& d1, float& d2, float& d3,
                                         uint32_t a0, uint32_t a1, uint32_t a2, uint32_t a3,
                                         uint32_t b0, uint32_t b1) {
    asm volatile(
        "mma.sync.aligned.m16n8k16.row.col.f32.f16.f16.f32 "
        "{%0,%1,%2,%3},{%4,%5,%6,%7},{%8,%9},{%0,%1,%2,%3};"
        : "+f"(d0), "+f"(d1), "+f"(d2), "+f"(d3)
        : "r"(a0), "r"(a1), "r"(a2), "r"(a3), "r"(b0), "r"(b1));
}

__device__ __forceinline__ float hswish_f(float x) {
    return x * fminf(fmaxf(x + 3.f, 0.f), 6.f) * (1.f / 6.f);
}

// ---------------- prep: interleave ref/oth into half2 channel-pair planar ----------------
__global__ void prep_interleave(const float* __restrict__ ref, const float* __restrict__ oth,
                                uint32_t* __restrict__ refI, uint32_t* __restrict__ othI) {
    size_t i = (size_t)blockIdx.x * 256 + threadIdx.x;
    size_t px = i & (HW - 1);
    size_t rest = i >> 14;
    size_t p = rest & 63;
    size_t b = rest >> 6;
    size_t s0 = (b * 128 + 2 * p) * HW + px;
    refI[i] = packh2(ref[s0], ref[s0 + HW]);
    othI[i] = packh2(oth[s0], oth[s0 + HW]);
}

// ---------------- prep: 3 conv weight sets -> fp16 fragment-packed uint4 ----------------
__global__ void prep_conv_frag_h3(const float* __restrict__ wq, const float* __restrict__ wk,
                                  const float* __restrict__ wv, uint4* __restrict__ out) {
    int which = blockIdx.y;
    const float* w = (which == 0) ? wq : (which == 1) ? wk : wv;
    uint4* o = out + (size_t)which * 18432;
    int j = blockIdx.x * 256 + threadIdx.x;
    int lane = j & 31, mi = (j >> 5) & 1, w2 = (j >> 6) & 1;
    int r3 = j >> 7;
    int rs = r3 % 9;
    int tmp = r3 / 9;
    int c016 = tmp & 7;
    int cb2 = tmp >> 3;
    int g = lane >> 2, t = lane & 3;
    int m = cb2 * 64 + w2 * 32 + mi * 16 + g;
    int k0 = c016 * 16 + 2 * t;
    uint4 u;
    u.x = packh2(w[((size_t)m * 128 + k0) * 9 + rs],       w[((size_t)m * 128 + k0 + 1) * 9 + rs]);
    u.y = packh2(w[((size_t)(m + 8) * 128 + k0) * 9 + rs], w[((size_t)(m + 8) * 128 + k0 + 1) * 9 + rs]);
    u.z = packh2(w[((size_t)m * 128 + k0 + 8) * 9 + rs],   w[((size_t)m * 128 + k0 + 9) * 9 + rs]);
    u.w = packh2(w[((size_t)(m + 8) * 128 + k0 + 8) * 9 + rs], w[((size_t)(m + 8) * 128 + k0 + 9) * 9 + rs]);
    o[j] = u;
}

// ---------------- prep: 1x1 weights -> fp16 fragment-packed uint4 ----------------
__global__ void prep_gemm_frag_h(const float* __restrict__ w, uint4* __restrict__ out,
                                 int Cin, int Cout) {
    int j = blockIdx.x * 256 + threadIdx.x;
    if (j >= (Cin * Cout) / 8) return;
    int lane = j & 31, mi = (j >> 5) & 1, w2 = (j >> 6) & 1;
    int rest = j >> 7;
    int nk = Cin >> 4;
    int k016 = rest % nk;
    int cb = rest / nk;
    int g = lane >> 2, t = lane & 3;
    int m = cb * 64 + w2 * 32 + mi * 16 + g;
    int k0 = k016 * 16 + 2 * t;
    uint4 u;
    u.x = packh2(w[(size_t)m * Cin + k0],       w[(size_t)m * Cin + k0 + 1]);
    u.y = packh2(w[(size_t)(m + 8) * Cin + k0], w[(size_t)(m + 8) * Cin + k0 + 1]);
    u.z = packh2(w[(size_t)m * Cin + k0 + 8],   w[(size_t)m * Cin + k0 + 9]);
    u.w = packh2(w[(size_t)(m + 8) * Cin + k0 + 8], w[(size_t)(m + 8) * Cin + k0 + 9]);
    out[j] = u;
}

// ---------------- fused 3x3 convs (q,k,v), M=128/block, 2-stage pipeline ----------------
__global__ void __launch_bounds__(256, 2)
conv3x3_tc(const uint32_t* __restrict__ refI, const uint32_t* __restrict__ othI,
           const uint4* __restrict__ wfragAll,
           const float* __restrict__ bq, const float* __restrict__ bk,
           const float* __restrict__ bv, __half* __restrict__ out) {
    extern __shared__ char smem_raw[];
    uint4* AfragB = (uint4*)smem_raw;                        // [2][2304]
    uint32_t* IshB = (uint32_t*)(smem_raw + 2 * 2304 * 16);  // [2][8*3*136]
    int tid = threadIdx.x;
    int lane = tid & 31, warp = tid >> 5;
    int g = lane >> 2, t = lane & 3;
    int w2 = warp >> 2;
    int wn = (warp & 3) * 32;
    int y = blockIdx.x;
    int cv = blockIdx.y;
    int b = blockIdx.z;
    const uint32_t* inI = (cv == 0) ? refI : othI;
    const uint4* wf = wfragAll + (size_t)cv * 18432;
    const float* bias = (cv == 0) ? bq : (cv == 1) ? bk : bv;
    int outOff = cv * 128;
    const uint32_t* inB = inI + (size_t)b * 64 * HW;
    float acc[4][4][4] = {};

    auto loadStage = [&](int c016, int buf) {
        uint4* A = AfragB + buf * 2304;
        uint32_t* I = IshB + buf * 3264;
        for (int j = tid; j < 1152; j += 256) {
            A[j] = wf[c016 * 1152 + j];
            A[j + 1152] = wf[9216 + c016 * 1152 + j];
        }
        const uint32_t* inP = inB + (size_t)(c016 * 8 + warp) * HW;
#pragma unroll
        for (int r = 0; r < 3; r++) {
            int yy = y - 1 + r;
            for (int col = lane; col < 130; col += 32) {
                int xx = col - 1;
                uint32_t v = 0u;
                if (xx >= 0 && xx < WW && yy >= 0 && yy < HH)
                    v = inP[yy * WW + xx];
                I[(warp * 3 + r) * 136 + col] = v;
            }
        }
    };

    loadStage(0, 0);
    for (int c016 = 0; c016 < 8; c016++) {
        __syncthreads();
        if (c016 < 7) loadStage(c016 + 1, (c016 + 1) & 1);
        const uint4* A = AfragB + (c016 & 1) * 2304;
        const uint32_t* I = IshB + (c016 & 1) * 3264;
#pragma unroll
        for (int r = 0; r < 3; r++) {
#pragma unroll
            for (int s = 0; s < 3; s++) {
                int rs = r * 3 + s;
                uint4 af[4];
#pragma unroll
                for (int mi2 = 0; mi2 < 4; mi2++)
                    af[mi2] = A[(mi2 >> 1) * 1152 +
                                ((rs * 2 + w2) * 2 + (mi2 & 1)) * 32 + lane];
#pragma unroll
                for (int ni = 0; ni < 4; ni++) {
                    uint32_t b0 = I[(t * 3 + r) * 136 + wn + ni * 8 + g + s];
                    uint32_t b1 = I[((t + 4) * 3 + r) * 136 + wn + ni * 8 + g + s];
#pragma unroll
                    for (int mi2 = 0; mi2 < 4; mi2++)
                        mma_fp16(acc[mi2][ni][0], acc[mi2][ni][1],
                                 acc[mi2][ni][2], acc[mi2][ni][3],
                                 af[mi2].x, af[mi2].y, af[mi2].z, af[mi2].w, b0, b1);
                }
            }
        }
    }
#pragma unroll
    for (int mi2 = 0; mi2 < 4; mi2++) {
        int co0 = (mi2 >> 1) * 64 + w2 * 32 + (mi2 & 1) * 16 + g;
        int co1 = co0 + 8;
        float bv0 = bias[co0], bv1 = bias[co1];
        __half* p0 = out + ((size_t)b * 768 + outOff + co0) * HW + y * WW;
        __half* p1 = out + ((size_t)b * 768 + outOff + co1) * HW + y * WW;
#pragma unroll
        for (int ni = 0; ni < 4; ni++) {
            int x0 = wn + ni * 8 + 2 * t;
            *(__half2*)&p0[x0] = __floats2half2_rn(acc[mi2][ni][0] + bv0, acc[mi2][ni][1] + bv0);
            *(__half2*)&p1[x0] = __floats2half2_rn(acc[mi2][ni][2] + bv1, acc[mi2][ni][3] + bv1);
        }
    }
}

// ---------------- 1x1 conv (GEMM), 128 couts x 256 pixels per block, 512 threads ----------------
// INKIND: 0 = fp32 planar, 2 = half2 pair-interleaved.  TO: float or __half.
template <int MODE, int INKIND, typename TO>
__global__ void __launch_bounds__(512, 1)
gemm1x1_tc(const void* __restrict__ in, int Cin,
           const uint4* __restrict__ wfrag, int Cout,
           const float* __restrict__ p0, const float* __restrict__ p1,
           const float* __restrict__ p2, const float* __restrict__ p3,
           const float* __restrict__ res, TO* __restrict__ out) {
    __shared__ uint4 Af[2][256];
    __shared__ uint32_t Ish[2][8][264];
    int tid = threadIdx.x;
    int lane = tid & 31, warp = tid >> 5;
    int g = lane >> 2, t = lane & 3;
    int w2 = warp >> 3;                 // 0/1 -> M halves
    int wn = (warp & 7) * 32;           // 0..224
    int nbase = blockIdx.x * 256;
    int cbBase = blockIdx.y * 2;
    int b = blockIdx.z;
    int nk = Cin >> 4;
    const float* inF = (const float*)in + (size_t)b * Cin * HW + nbase;
    const uint32_t* inP = (const uint32_t*)in + (size_t)b * (Cin / 2) * HW + nbase;
    float acc[4][4][4] = {};

    auto loadStage = [&](int k016, int buf) {
        if (tid < 256) {
            int half = tid >> 7;
            int idx = tid & 127;
            Af[buf][tid] = wfrag[((size_t)(cbBase + half) * nk + k016) * 128 + idx];
        }
        int k2 = tid >> 6, p2i = tid & 63;
        if constexpr (INKIND == 0) {
            int k0 = k016 * 16;
            const float* r0 = inF + (size_t)(k0 + 2 * k2) * HW + p2i * 4;
            float4 v0 = *(const float4*)r0;
            float4 v1 = *(const float4*)(r0 + HW);
            uint4 o;
            o.x = packh2(v0.x, v1.x);
            o.y = packh2(v0.y, v1.y);
            o.z = packh2(v0.z, v1.z);
            o.w = packh2(v0.w, v1.w);
            *(uint4*)&Ish[buf][k2][p2i * 4] = o;
        } else {
            const uint32_t* r0 = inP + (size_t)(k016 * 8 + k2) * HW + p2i * 4;
            *(uint4*)&Ish[buf][k2][p2i * 4] = *(const uint4*)r0;
        }
    };

    loadStage(0, 0);
    for (int k016 = 0; k016 < nk; k016++) {
        __syncthreads();
        if (k016 + 1 < nk) loadStage(k016 + 1, (k016 + 1) & 1);
        int buf = k016 & 1;
        uint4 af[4];
#pragma unroll
        for (int mi2 = 0; mi2 < 4; mi2++)
            af[mi2] = Af[buf][(mi2 >> 1) * 128 + (w2 * 2 + (mi2 & 1)) * 32 + lane];
#pragma unroll
        for (int ni = 0; ni < 4; ni++) {
            uint32_t b0 = Ish[buf][t][wn + ni * 8 + g];
            uint32_t b1 = Ish[buf][t + 4][wn + ni * 8 + g];
#pragma unroll
            for (int mi2 = 0; mi2 < 4; mi2++)
                mma_fp16(acc[mi2][ni][0], acc[mi2][ni][1], acc[mi2][ni][2], acc[mi2][ni][3],
                         af[mi2].x, af[mi2].y, af[mi2].z, af[mi2].w, b0, b1);
        }
    }
    // epilogue
#pragma unroll
    for (int mi2 = 0; mi2 < 4; mi2++) {
        int co0 = (cbBase + (mi2 >> 1)) * 64 + w2 * 32 + (mi2 & 1) * 16 + g;
        int co1 = co0 + 8;
        float b0v = 0.f, b1v = 0.f, sc0 = 0.f, sc1 = 0.f, sh0 = 0.f, sh1 = 0.f;
        if (MODE == 0) {
            b0v = p0[co0];
            b1v = p0[co1];
        } else {
            sc0 = p0[co0] * rsqrtf(p3[co0] + 1e-5f);
            sh0 = p1[co0] - p2[co0] * sc0;
            sc1 = p0[co1] * rsqrtf(p3[co1] + 1e-5f);
            sh1 = p1[co1] - p2[co1] * sc1;
        }
        size_t row0 = ((size_t)b * Cout + co0) * HW + nbase;
        size_t row1 = ((size_t)b * Cout + co1) * HW + nbase;
#pragma unroll
        for (int ni = 0; ni < 4; ni++) {
            int x0 = wn + ni * 8 + 2 * t;
            float v00 = acc[mi2][ni][0], v01 = acc[mi2][ni][1];
            float v10 = acc[mi2][ni][2], v11 = acc[mi2][ni][3];
            if (MODE == 0) {
                v00 = hswish_f(v00 + b0v);
                v01 = hswish_f(v01 + b0v);
                v10 = hswish_f(v10 + b1v);
                v11 = hswish_f(v11 + b1v);
            } else {
                float2 r0 = *(const float2*)&res[row0 + x0];
                float2 r1 = *(const float2*)&res[row1 + x0];
                v00 = v00 * sc0 + sh0 + r0.x;
                v01 = v01 * sc0 + sh0 + r0.y;
                v10 = v10 * sc1 + sh1 + r1.x;
                v11 = v11 * sc1 + sh1 + r1.y;
            }
            if constexpr (sizeof(TO) == 4) {
                *(float2*)&((float*)out)[row0 + x0] = make_float2(v00, v01);
                *(float2*)&((float*)out)[row1 + x0] = make_float2(v10, v11);
            } else {
                *(__half2*)&((__half*)out)[row0 + x0] = __floats2half2_rn(v00, v01);
                *(__half2*)&((__half*)out)[row1 + x0] = __floats2half2_rn(v10, v11);
            }
        }
    }
}

// ---------------- 5x5 depthwise, channel pair, 8 rows per block (fp16 io) ----------------
__global__ void dw5x5_k(const __half* __restrict__ in, const float* __restrict__ wgt,
                        __half* __restrict__ out) {
    __shared__ float sh[2][12][136];
    int tid = threadIdx.x;
    int warp = tid >> 5, lane = tid & 31;
    int y0 = blockIdx.x * 8;
    int cp = blockIdx.y;
    int b = blockIdx.z;
    const __half* inC = in + ((size_t)b * 768 + 2 * cp) * HW;
    for (int rr = warp; rr < 24; rr += 8) {
        int ch = rr / 12, row = rr % 12;
        int yy = y0 - 2 + row;
        const __half* ip = inC + (size_t)ch * HW;
        for (int col = lane; col < 132; col += 32) {
            int xx = col - 2;
            float v = 0.f;
            if (yy >= 0 && yy < HH && xx >= 0 && xx < WW) v = __half2float(ip[yy * WW + xx]);
            sh[ch][row][col] = v;
        }
    }
    __syncthreads();
    float w0[25], w1[25];
#pragma unroll
    for (int i = 0; i < 25; i++) {
        w0[i] = wgt[(2 * cp) * 25 + i];
        w1[i] = wgt[(2 * cp + 1) * 25 + i];
    }
    __half* oC0 = out + ((size_t)b * 384 + 2 * cp) * HW;
    __half* oC1 = oC0 + HW;
#pragma unroll
    for (int p = 0; p < 4; p++) {
        int px = tid + p * 256;
        int ry = px >> 7, x = px & 127;
        float a0 = 0.f, a1 = 0.f;
#pragma unroll
        for (int r = 0; r < 5; r++)
#pragma unroll
            for (int s = 0; s < 5; s++) {
                a0 += w0[r * 5 + s] * sh[0][ry + r][x + s];
                a1 += w1[r * 5 + s] * sh[1][ry + r][x + s];
            }
        oC0[(y0 + ry) * WW + x] = __float2half(a0);
        oC1[(y0 + ry) * WW + x] = __float2half(a1);
    }
}

// ---------------- grouped 1x1, 8->8 per group, 2 pixels/thread (half2 io) ----------------
__global__ void pw_group_k(const uint32_t* __restrict__ in, const float* __restrict__ wgt,
                           uint32_t* __restrict__ out) {
    __shared__ float wsh[64];
    int g = blockIdx.y;
    int b = blockIdx.z;
    if (threadIdx.x < 64) wsh[threadIdx.x] = wgt[g * 64 + threadIdx.x];
    __syncthreads();
    int n2 = blockIdx.x * 256 + threadIdx.x;
    const uint32_t* ip = in + ((size_t)b * 384 + g * 8) * (HW / 2) + n2;
    float2 xi[8];
#pragma unroll
    for (int i = 0; i < 8; i++) {
        __half2 h = *(const __half2*)&ip[(size_t)i * (HW / 2)];
        xi[i] = __half22float2(h);
    }
    uint32_t* op = out + ((size_t)b * 768 + 384 + g * 8) * (HW / 2) + n2;
#pragma unroll
    for (int o = 0; o < 8; o++) {
        float a0 = 0.f, a1 = 0.f;
#pragma unroll
        for (int i = 0; i < 8; i++) {
            a0 += wsh[o * 8 + i] * xi[i].x;
            a1 += wsh[o * 8 + i] * xi[i].y;
        }
        op[(size_t)o * (HW / 2)] = packh2(a0, a1);
    }
}

// ---------------- attention phase 1: partial kv per chunk (no atomics) ----------------
__global__ void attn_kv_k(const __half* __restrict__ multi, float* __restrict__ kv) {
    int b = blockIdx.z, g = blockIdx.y;
    int chunk = blockIdx.x;
    const __half* base = multi + ((size_t)b * 768 + g * 24) * HW;
    int n0 = chunk * 8192;
    float acc[72];
#pragma unroll
    for (int i = 0; i < 72; i++) acc[i] = 0.f;
    for (int n = n0 + 2 * threadIdx.x; n < n0 + 8192; n += 512) {
        float2 kq[8], vv[8];
#pragma unroll
        for (int j = 0; j < 8; j++) {
            __half2 h = *(const __half2*)&base[(size_t)(8 + j) * HW + n];
            float2 f = __half22float2(h);
            kq[j].x = fmaxf(f.x, 0.f);
            kq[j].y = fmaxf(f.y, 0.f);
        }
#pragma unroll
        for (int e = 0; e < 8; e++) {
            __half2 h = *(const __half2*)&base[(size_t)(16 + e) * HW + n];
            vv[e] = __half22float2(h);
        }
#pragma unroll
        for (int e = 0; e < 8; e++)
#pragma unroll
            for (int j = 0; j < 8; j++)
                acc[e * 8 + j] += vv[e].x * kq[j].x + vv[e].y * kq[j].y;
#pragma unroll
        for (int j = 0; j < 8; j++) acc[64 + j] += kq[j].x + kq[j].y;
    }
    __shared__ float red[72][8];
    int lane = threadIdx.x & 31, warp = threadIdx.x >> 5;
#pragma unroll
    for (int i = 0; i < 72; i++) {
        float v = acc[i];
        v += __shfl_down_sync(0xffffffffu, v, 16);
        v += __shfl_down_sync(0xffffffffu, v, 8);
        v += __shfl_down_sync(0xffffffffu, v, 4);
        v += __shfl_down_sync(0xffffffffu, v, 2);
        v += __shfl_down_sync(0xffffffffu, v, 1);
        if (lane == 0) red[i][warp] = v;
    }
    __syncthreads();
    if (threadIdx.x < 72) {
        float s = 0.f;
#pragma unroll
        for (int w = 0; w < 8; w++) s += red[threadIdx.x][w];
        kv[(((size_t)b * 32 + g) * 2 + chunk) * 72 + threadIdx.x] = s;
    }
}

// ---------------- attention phase 2: 2 pixels/thread, half2-pair out ----------------
__global__ void attn_apply_k(const __half* __restrict__ multi, const float* __restrict__ kv,
                             uint32_t* __restrict__ attI) {
    int b = blockIdx.z, g = blockIdx.y;
    __shared__ float kvs[72];
    if (threadIdx.x < 72) {
        const float* kvp = kv + ((size_t)b * 32 + g) * 2 * 72 + threadIdx.x;
        kvs[threadIdx.x] = kvp[0] + kvp[72];
    }
    __syncthreads();
    int n = (blockIdx.x * 256 + threadIdx.x) * 2;
    const __half* base = multi + ((size_t)b * 768 + g * 24) * HW + n;
    float2 q[8];
#pragma unroll
    for (int j = 0; j < 8; j++) {
        __half2 h = *(const __half2*)&base[(size_t)j * HW];
        float2 f = __half22float2(h);
        q[j].x = fmaxf(f.x, 0.f);
        q[j].y = fmaxf(f.y, 0.f);
    }
    float d0 = 0.f, d1 = 0.f;
#pragma unroll
    for (int j = 0; j < 8; j++) {
        d0 += kvs[64 + j] * q[j].x;
        d1 += kvs[64 + j] * q[j].y;
    }
    float inv0 = 1.f / (d0 + 1e-15f);
    float inv1 = 1.f / (d1 + 1e-15f);
    uint32_t* op = attI + ((size_t)b * 128 + g * 4) * HW + n;
#pragma unroll
    for (int e2 = 0; e2 < 4; e2++) {
        float sa0 = 0.f, sb0 = 0.f, sa1 = 0.f, sb1 = 0.f;
#pragma unroll
        for (int j = 0; j < 8; j++) {
            float ka = kvs[(2 * e2) * 8 + j], kb = kvs[(2 * e2 + 1) * 8 + j];
            sa0 += ka * q[j].x;
            sb0 += kb * q[j].x;
            sa1 += ka * q[j].y;
            sb1 += kb * q[j].y;
        }
        uint2 o;
        o.x = packh2(sa0 * inv0, sb0 * inv0);
        o.y = packh2(sa1 * inv1, sb1 * inv1);
        *(uint2*)&op[(size_t)e2 * HW] = o;
    }
}

// ---------------- 3x3 dw + bias + hswish, channel PAIR per block, half2 out ----------------
__global__ void dw3x3_k(const __half* __restrict__ in, const float* __restrict__ wgt,
                        const float* __restrict__ bias, uint32_t* __restrict__ outI) {
    __shared__ float sh[2][10][136];
    int tid = threadIdx.x;
    int warp = tid >> 5, lane = tid & 31;
    int y0 = blockIdx.x * 8;
    int cp = blockIdx.y;
    int b = blockIdx.z;
    const __half* inC = in + ((size_t)b * 768 + 2 * cp) * HW;
    for (int rr = warp; rr < 20; rr += 8) {
        int ch = rr / 10, row = rr % 10;
        int yy = y0 - 1 + row;
        const __half* ip = inC + (size_t)ch * HW;
        for (int col = lane; col < 130; col += 32) {
            int xx = col - 1;
            float v = 0.f;
            if (yy >= 0 && yy < HH && xx >= 0 && xx < WW) v = __half2float(ip[yy * WW + xx]);
            sh[ch][row][col] = v;
        }
    }
    __syncthreads();
    float w0[9], w1[9];
#pragma unroll
    for (int i = 0; i < 9; i++) {
        w0[i] = wgt[(2 * cp) * 9 + i];
        w1[i] = wgt[(2 * cp + 1) * 9 + i];
    }
    float bv0 = bias[2 * cp], bv1 = bias[2 * cp + 1];
    uint32_t* oC = outI + ((size_t)b * 384 + cp) * HW;
#pragma unroll
    for (int p = 0; p < 4; p++) {
        int px = tid + p * 256;
        int ry = px >> 7, x = px & 127;
        float a0 = bv0, a1 = bv1;
#pragma unroll
        for (int r = 0; r < 3; r++)
#pragma unroll
            for (int s = 0; s < 3; s++) {
                a0 += w0[r * 3 + s] * sh[0][ry + r][x + s];
                a1 += w1[r * 3 + s] * sh[1][ry + r][x + s];
            }
        oC[(y0 + ry) * WW + x] = packh2(hswish_f(a0), hswish_f(a1));
    }
}

// ---------------- launch ----------------
extern "C" void kernel_launch(void* const* d_in, const int* in_sizes, int n_in,
                              void* d_out, int out_size) {
    const float* ref = (const float*)d_in[0];
    const float* oth = (const float*)d_in[1];
    const float* wq = (const float*)d_in[2];
    const float* bq = (const float*)d_in[3];
    const float* wk = (const float*)d_in[4];
    const float* bk = (const float*)d_in[5];
    const float* wv = (const float*)d_in[6];
    const float* bv = (const float*)d_in[7];
    const float* agg_dw_w = (const float*)d_in[8];
    const float* agg_pw_w = (const float*)d_in[9];
    const float* attn_proj_w = (const float*)d_in[10];
    const float* bn1_g = (const float*)d_in[11];
    const float* bn1_b = (const float*)d_in[12];
    const float* bn1_m = (const float*)d_in[13];
    const float* bn1_v = (const float*)d_in[14];
    const float* mb1_w = (const float*)d_in[15];
    const float* mb1_b = (const float*)d_in[16];
    const float* mb2_w = (const float*)d_in[17];
    const float* mb2_b = (const float*)d_in[18];
    const float* mb3_w = (const float*)d_in[19];
    const float* bn2_g = (const float*)d_in[20];
    const float* bn2_b = (const float*)d_in[21];
    const float* bn2_m = (const float*)d_in[22];
    const float* bn2_v = (const float*)d_in[23];

    __half *multi, *msdw, *h1;
    uint32_t *atti, *h2i, *refi, *othi;
    float *attended, *kv, *wT;
    cudaGetSymbolAddress((void**)&multi, g_multi);
    cudaGetSymbolAddress((void**)&msdw, g_msdw);
    cudaGetSymbolAddress((void**)&atti, g_atti);
    cudaGetSymbolAddress((void**)&attended, g_attended);
    cudaGetSymbolAddress((void**)&h1, g_h1);
    cudaGetSymbolAddress((void**)&h2i, g_h2i);
    cudaGetSymbolAddress((void**)&kv, g_kv);
    cudaGetSymbolAddress((void**)&wT, g_wT);
    cudaGetSymbolAddress((void**)&refi, g_refi);
    cudaGetSymbolAddress((void**)&othi, g_othi);
    uint4* fr4 = (uint4*)wT;

    static bool attr_set = false;
    if (!attr_set) {
        cudaFuncSetAttribute(conv3x3_tc, cudaFuncAttributeMaxDynamicSharedMemorySize,
                             CONV_SMEM);
        attr_set = true;
    }

    // prep: interleave inputs + weight fragment packing
    prep_interleave<<<BB * 64 * HW / 256, 256>>>(ref, oth, refi, othi);
    prep_conv_frag_h3<<<dim3(72, 3), 256>>>(wq, wk, wv, fr4 + FQ);
    prep_gemm_frag_h<<<16, 256>>>(attn_proj_w, fr4 + FP, 256, 128);
    prep_gemm_frag_h<<<48, 256>>>(mb1_w, fr4 + F1, 128, 768);
    prep_gemm_frag_h<<<48, 256>>>(mb3_w, fr4 + F3, 768, 128);

    // fused q,k,v 3x3 convs (M=128/block, pipelined) -> multi channels 0/128/256
    conv3x3_tc<<<dim3(128, 3, 4), 256, CONV_SMEM>>>(refi, othi, fr4 + FQ, bq, bk, bv, multi);

    // aggregation: 5x5 dw (channel pair, 8 rows/block) then grouped 1x1
    dw5x5_k<<<dim3(16, 192, 4), 256>>>(multi, agg_dw_w, msdw);
    pw_group_k<<<dim3(32, 48, 4), 256>>>((const uint32_t*)msdw, agg_pw_w, (uint32_t*)multi);

    // relu linear attention (fp16 io, fp32 accum, partial-kv no atomics)
    attn_kv_k<<<dim3(2, 32, 4), 256>>>(multi, kv);
    attn_apply_k<<<dim3(32, 32, 4), 256>>>(multi, kv, atti);

    // attn_proj + bn1 + residual(ref fp32) -> attended (fp32)
    gemm1x1_tc<1, 2, float><<<dim3(64, 1, 4), 512>>>(
        atti, 256, fr4 + FP, 128, bn1_g, bn1_b, bn1_m, bn1_v, ref, attended);

    // MBConv
    gemm1x1_tc<0, 0, __half><<<dim3(64, 6, 4), 512>>>(
        attended, 128, fr4 + F1, 768, mb1_b, nullptr, nullptr, nullptr, nullptr, h1);
    dw3x3_k<<<dim3(16, 384, 4), 256>>>(h1, mb2_w, mb2_b, h2i);
    gemm1x1_tc<1, 2, float><<<dim3(64, 1, 4), 512>>>(
        h2i, 768, fr4 + F3, 128, bn2_g, bn2_b, bn2_m, bn2_v, attended, (float*)d_out);
}

// round 17
// speedup vs baseline: 1.0411x; 1.0411x over previous
#include <cuda_runtime.h>
#include <cuda_fp16.h>
#include <cstdint>
#include <cstddef>

#define HH 128
#define WW 128
#define HW 16384
#define BB 4

// ---------------- scratch (static device globals; no allocation) ----------------
__device__ __half   g_multi[(size_t)BB * 768 * HW];   // qkv (0..383) + ms (384..767), planar
__device__ __half   g_msdw[(size_t)BB * 384 * HW];    // depthwise 5x5 output, planar
__device__ uint32_t g_atti[(size_t)BB * 128 * HW];    // attention output, half2 pairs
__device__ float    g_attended[(size_t)BB * 128 * HW];// residual branch point (fp32)
__device__ __half   g_h1[(size_t)BB * 768 * HW];      // mb1 output, planar
__device__ uint32_t g_h2i[(size_t)BB * 384 * HW];     // mb2 output, half2 pairs
__device__ float    g_kv[(size_t)BB * 32 * 2 * 72];   // per-(b,g,chunk) partial kv
__device__ float    g_wT[768 * 1152];                 // fragment-packed fp16 weights (uint4 view)
__device__ uint32_t g_refi[(size_t)BB * 64 * HW];     // ref as half2 channel pairs
__device__ uint32_t g_othi[(size_t)BB * 64 * HW];     // oth as half2 channel pairs

// fragment-region offsets in uint4 units
#define FQ 0
#define FK 18432
#define FV 36864
#define FP 55296
#define F1 59392
#define F3 71680

// conv dynamic smem: Afrag [2][2304] uint4 + Ish [2][8*3*136] uint32
#define CONV_SMEM (2 * 2304 * 16 + 2 * 3264 * 4)

// ---------------- fp16 mma helpers ----------------
__device__ __forceinline__ uint32_t packh2(float a, float b) {
    __half2 h = __floats2half2_rn(a, b);
    return *(uint32_t*)&h;
}

__device__ __forceinline__ void mma_fp16(float& d0, float& d1, float& d2, float& d3,
                                         uint32_t a0, uint32_t a1, uint32_t a2, uint32_t a3,
                                         uint32_t b0, uint32_t b1) {
    asm volatile(
        "mma.sync.aligned.m16n8k16.row.col.f32.f16.f16.f32 "
        "{%0,%1,%2,%3},{%4,%5,%6,%7},{%8,%9},{%0,%1,%2,%3};"
        : "+f"(d0), "+f"(d1), "+f"(d2), "+f"(d3)
        : "r"(a0), "r"(a1), "r"(a2), "r"(a3), "r"(b0), "r"(b1));
}

__device__ __forceinline__ float hswish_f(float x) {
    return x * fminf(fmaxf(x + 3.f, 0.f), 6.f) * (1.f / 6.f);
}

// ---------------- prep: interleave ref/oth into half2 channel-pair planar ----------------
__global__ void prep_interleave(const float* __restrict__ ref, const float* __restrict__ oth,
                                uint32_t* __restrict__ refI, uint32_t* __restrict__ othI) {
    size_t i = (size_t)blockIdx.x * 256 + threadIdx.x;
    size_t px = i & (HW - 1);
    size_t rest = i >> 14;
    size_t p = rest & 63;
    size_t b = rest >> 6;
    size_t s0 = (b * 128 + 2 * p) * HW + px;
    refI[i] = packh2(ref[s0], ref[s0 + HW]);
    othI[i] = packh2(oth[s0], oth[s0 + HW]);
}

// ---------------- prep: 3 conv weight sets -> fp16 fragment-packed uint4 ----------------
__global__ void prep_conv_frag_h3(const float* __restrict__ wq, const float* __restrict__ wk,
                                  const float* __restrict__ wv, uint4* __restrict__ out) {
    int which = blockIdx.y;
    const float* w = (which == 0) ? wq : (which == 1) ? wk : wv;
    uint4* o = out + (size_t)which * 18432;
    int j = blockIdx.x * 256 + threadIdx.x;
    int lane = j & 31, mi = (j >> 5) & 1, w2 = (j >> 6) & 1;
    int r3 = j >> 7;
    int rs = r3 % 9;
    int tmp = r3 / 9;
    int c016 = tmp & 7;
    int cb2 = tmp >> 3;
    int g = lane >> 2, t = lane & 3;
    int m = cb2 * 64 + w2 * 32 + mi * 16 + g;
    int k0 = c016 * 16 + 2 * t;
    uint4 u;
    u.x = packh2(w[((size_t)m * 128 + k0) * 9 + rs],       w[((size_t)m * 128 + k0 + 1) * 9 + rs]);
    u.y = packh2(w[((size_t)(m + 8) * 128 + k0) * 9 + rs], w[((size_t)(m + 8) * 128 + k0 + 1) * 9 + rs]);
    u.z = packh2(w[((size_t)m * 128 + k0 + 8) * 9 + rs],   w[((size_t)m * 128 + k0 + 9) * 9 + rs]);
    u.w = packh2(w[((size_t)(m + 8) * 128 + k0 + 8) * 9 + rs], w[((size_t)(m + 8) * 128 + k0 + 9) * 9 + rs]);
    o[j] = u;
}

// ---------------- prep: 1x1 weights -> fp16 fragment-packed uint4 ----------------
__global__ void prep_gemm_frag_h(const float* __restrict__ w, uint4* __restrict__ out,
                                 int Cin, int Cout) {
    int j = blockIdx.x * 256 + threadIdx.x;
    if (j >= (Cin * Cout) / 8) return;
    int lane = j & 31, mi = (j >> 5) & 1, w2 = (j >> 6) & 1;
    int rest = j >> 7;
    int nk = Cin >> 4;
    int k016 = rest % nk;
    int cb = rest / nk;
    int g = lane >> 2, t = lane & 3;
    int m = cb * 64 + w2 * 32 + mi * 16 + g;
    int k0 = k016 * 16 + 2 * t;
    uint4 u;
    u.x = packh2(w[(size_t)m * Cin + k0],       w[(size_t)m * Cin + k0 + 1]);
    u.y = packh2(w[(size_t)(m + 8) * Cin + k0], w[(size_t)(m + 8) * Cin + k0 + 1]);
    u.z = packh2(w[(size_t)m * Cin + k0 + 8],   w[(size_t)m * Cin + k0 + 9]);
    u.w = packh2(w[(size_t)(m + 8) * Cin + k0 + 8], w[(size_t)(m + 8) * Cin + k0 + 9]);
    out[j] = u;
}

// ---------------- fused 3x3 convs (q,k,v), M=128/block, 2-stage pipeline ----------------
__global__ void __launch_bounds__(256, 2)
conv3x3_tc(const uint32_t* __restrict__ refI, const uint32_t* __restrict__ othI,
           const uint4* __restrict__ wfragAll,
           const float* __restrict__ bq, const float* __restrict__ bk,
           const float* __restrict__ bv, __half* __restrict__ out) {
    extern __shared__ char smem_raw[];
    uint4* AfragB = (uint4*)smem_raw;                        // [2][2304]
    uint32_t* IshB = (uint32_t*)(smem_raw + 2 * 2304 * 16);  // [2][8*3*136]
    int tid = threadIdx.x;
    int lane = tid & 31, warp = tid >> 5;
    int g = lane >> 2, t = lane & 3;
    int w2 = warp >> 2;
    int wn = (warp & 3) * 32;
    int y = blockIdx.x;
    int cv = blockIdx.y;
    int b = blockIdx.z;
    const uint32_t* inI = (cv == 0) ? refI : othI;
    const uint4* wf = wfragAll + (size_t)cv * 18432;
    const float* bias = (cv == 0) ? bq : (cv == 1) ? bk : bv;
    int outOff = cv * 128;
    const uint32_t* inB = inI + (size_t)b * 64 * HW;
    float acc[4][4][4] = {};

    auto loadStage = [&](int c016, int buf) {
        uint4* A = AfragB + buf * 2304;
        uint32_t* I = IshB + buf * 3264;
        for (int j = tid; j < 1152; j += 256) {
            A[j] = wf[c016 * 1152 + j];
            A[j + 1152] = wf[9216 + c016 * 1152 + j];
        }
        const uint32_t* inP = inB + (size_t)(c016 * 8 + warp) * HW;
#pragma unroll
        for (int r = 0; r < 3; r++) {
            int yy = y - 1 + r;
            for (int col = lane; col < 130; col += 32) {
                int xx = col - 1;
                uint32_t v = 0u;
                if (xx >= 0 && xx < WW && yy >= 0 && yy < HH)
                    v = inP[yy * WW + xx];
                I[(warp * 3 + r) * 136 + col] = v;
            }
        }
    };

    loadStage(0, 0);
    for (int c016 = 0; c016 < 8; c016++) {
        __syncthreads();
        if (c016 < 7) loadStage(c016 + 1, (c016 + 1) & 1);
        const uint4* A = AfragB + (c016 & 1) * 2304;
        const uint32_t* I = IshB + (c016 & 1) * 3264;
#pragma unroll
        for (int r = 0; r < 3; r++) {
#pragma unroll
            for (int s = 0; s < 3; s++) {
                int rs = r * 3 + s;
                uint4 af[4];
#pragma unroll
                for (int mi2 = 0; mi2 < 4; mi2++)
                    af[mi2] = A[(mi2 >> 1) * 1152 +
                                ((rs * 2 + w2) * 2 + (mi2 & 1)) * 32 + lane];
#pragma unroll
                for (int ni = 0; ni < 4; ni++) {
                    uint32_t b0 = I[(t * 3 + r) * 136 + wn + ni * 8 + g + s];
                    uint32_t b1 = I[((t + 4) * 3 + r) * 136 + wn + ni * 8 + g + s];
#pragma unroll
                    for (int mi2 = 0; mi2 < 4; mi2++)
                        mma_fp16(acc[mi2][ni][0], acc[mi2][ni][1],
                                 acc[mi2][ni][2], acc[mi2][ni][3],
                                 af[mi2].x, af[mi2].y, af[mi2].z, af[mi2].w, b0, b1);
                }
            }
        }
    }
#pragma unroll
    for (int mi2 = 0; mi2 < 4; mi2++) {
        int co0 = (mi2 >> 1) * 64 + w2 * 32 + (mi2 & 1) * 16 + g;
        int co1 = co0 + 8;
        float bv0 = bias[co0], bv1 = bias[co1];
        __half* p0 = out + ((size_t)b * 768 + outOff + co0) * HW + y * WW;
        __half* p1 = out + ((size_t)b * 768 + outOff + co1) * HW + y * WW;
#pragma unroll
        for (int ni = 0; ni < 4; ni++) {
            int x0 = wn + ni * 8 + 2 * t;
            *(__half2*)&p0[x0] = __floats2half2_rn(acc[mi2][ni][0] + bv0, acc[mi2][ni][1] + bv0);
            *(__half2*)&p1[x0] = __floats2half2_rn(acc[mi2][ni][2] + bv1, acc[mi2][ni][3] + bv1);
        }
    }
}

// ---------------- 1x1 conv (GEMM), M=128/block, 2-stage pipeline (R14 version) ----------------
// INKIND: 0 = fp32 planar, 2 = half2 pair-interleaved.  TO: float or __half.
template <int MODE, int INKIND, typename TO>
__global__ void __launch_bounds__(256, 2)
gemm1x1_tc(const void* __restrict__ in, int Cin,
           const uint4* __restrict__ wfrag, int Cout,
           const float* __restrict__ p0, const float* __restrict__ p1,
           const float* __restrict__ p2, const float* __restrict__ p3,
           const float* __restrict__ res, TO* __restrict__ out) {
    __shared__ uint4 Af[2][256];
    __shared__ uint32_t Ish[2][8][136];
    int tid = threadIdx.x;
    int lane = tid & 31, warp = tid >> 5;
    int g = lane >> 2, t = lane & 3;
    int w2 = warp >> 2;
    int wn = (warp & 3) * 32;
    int nbase = blockIdx.x * 128;
    int cbBase = blockIdx.y * 2;
    int b = blockIdx.z;
    int nk = Cin >> 4;
    const float* inF = (const float*)in + (size_t)b * Cin * HW + nbase;
    const uint32_t* inP = (const uint32_t*)in + (size_t)b * (Cin / 2) * HW + nbase;
    float acc[4][4][4] = {};

    auto loadStage = [&](int k016, int buf) {
        int half = tid >> 7;
        int idx = tid & 127;
        Af[buf][tid] = wfrag[((size_t)(cbBase + half) * nk + k016) * 128 + idx];
        int k2 = tid >> 5, p2i = tid & 31;
        if constexpr (INKIND == 0) {
            int k0 = k016 * 16;
            const float* r0 = inF + (size_t)(k0 + 2 * k2) * HW + p2i * 4;
            float4 v0 = *(const float4*)r0;
            float4 v1 = *(const float4*)(r0 + HW);
            uint4 o;
            o.x = packh2(v0.x, v1.x);
            o.y = packh2(v0.y, v1.y);
            o.z = packh2(v0.z, v1.z);
            o.w = packh2(v0.w, v1.w);
            *(uint4*)&Ish[buf][k2][p2i * 4] = o;
        } else {
            const uint32_t* r0 = inP + (size_t)(k016 * 8 + k2) * HW + p2i * 4;
            *(uint4*)&Ish[buf][k2][p2i * 4] = *(const uint4*)r0;
        }
    };

    loadStage(0, 0);
    for (int k016 = 0; k016 < nk; k016++) {
        __syncthreads();
        if (k016 + 1 < nk) loadStage(k016 + 1, (k016 + 1) & 1);
        int buf = k016 & 1;
        uint4 af[4];
#pragma unroll
        for (int mi2 = 0; mi2 < 4; mi2++)
            af[mi2] = Af[buf][(mi2 >> 1) * 128 + (w2 * 2 + (mi2 & 1)) * 32 + lane];
#pragma unroll
        for (int ni = 0; ni < 4; ni++) {
            uint32_t b0 = Ish[buf][t][wn + ni * 8 + g];
            uint32_t b1 = Ish[buf][t + 4][wn + ni * 8 + g];
#pragma unroll
            for (int mi2 = 0; mi2 < 4; mi2++)
                mma_fp16(acc[mi2][ni][0], acc[mi2][ni][1], acc[mi2][ni][2], acc[mi2][ni][3],
                         af[mi2].x, af[mi2].y, af[mi2].z, af[mi2].w, b0, b1);
        }
    }
    // epilogue
#pragma unroll
    for (int mi2 = 0; mi2 < 4; mi2++) {
        int co0 = (cbBase + (mi2 >> 1)) * 64 + w2 * 32 + (mi2 & 1) * 16 + g;
        int co1 = co0 + 8;
        float b0v = 0.f, b1v = 0.f, sc0 = 0.f, sc1 = 0.f, sh0 = 0.f, sh1 = 0.f;
        if (MODE == 0) {
            b0v = p0[co0];
            b1v = p0[co1];
        } else {
            sc0 = p0[co0] * rsqrtf(p3[co0] + 1e-5f);
            sh0 = p1[co0] - p2[co0] * sc0;
            sc1 = p0[co1] * rsqrtf(p3[co1] + 1e-5f);
            sh1 = p1[co1] - p2[co1] * sc1;
        }
        size_t row0 = ((size_t)b * Cout + co0) * HW + nbase;
        size_t row1 = ((size_t)b * Cout + co1) * HW + nbase;
#pragma unroll
        for (int ni = 0; ni < 4; ni++) {
            int x0 = wn + ni * 8 + 2 * t;
            float v00 = acc[mi2][ni][0], v01 = acc[mi2][ni][1];
            float v10 = acc[mi2][ni][2], v11 = acc[mi2][ni][3];
            if (MODE == 0) {
                v00 = hswish_f(v00 + b0v);
                v01 = hswish_f(v01 + b0v);
                v10 = hswish_f(v10 + b1v);
                v11 = hswish_f(v11 + b1v);
            } else {
                float2 r0 = *(const float2*)&res[row0 + x0];
                float2 r1 = *(const float2*)&res[row1 + x0];
                v00 = v00 * sc0 + sh0 + r0.x;
                v01 = v01 * sc0 + sh0 + r0.y;
                v10 = v10 * sc1 + sh1 + r1.x;
                v11 = v11 * sc1 + sh1 + r1.y;
            }
            if constexpr (sizeof(TO) == 4) {
                *(float2*)&((float*)out)[row0 + x0] = make_float2(v00, v01);
                *(float2*)&((float*)out)[row1 + x0] = make_float2(v10, v11);
            } else {
                *(__half2*)&((__half*)out)[row0 + x0] = __floats2half2_rn(v00, v01);
                *(__half2*)&((__half*)out)[row1 + x0] = __floats2half2_rn(v10, v11);
            }
        }
    }
}

// ---------------- 5x5 depthwise, channel pair, 8 rows per block (fp16 io) ----------------
__global__ void dw5x5_k(const __half* __restrict__ in, const float* __restrict__ wgt,
                        __half* __restrict__ out) {
    __shared__ float sh[2][12][136];
    int tid = threadIdx.x;
    int warp = tid >> 5, lane = tid & 31;
    int y0 = blockIdx.x * 8;
    int cp = blockIdx.y;
    int b = blockIdx.z;
    const __half* inC = in + ((size_t)b * 768 + 2 * cp) * HW;
    for (int rr = warp; rr < 24; rr += 8) {
        int ch = rr / 12, row = rr % 12;
        int yy = y0 - 2 + row;
        const __half* ip = inC + (size_t)ch * HW;
        for (int col = lane; col < 132; col += 32) {
            int xx = col - 2;
            float v = 0.f;
            if (yy >= 0 && yy < HH && xx >= 0 && xx < WW) v = __half2float(ip[yy * WW + xx]);
            sh[ch][row][col] = v;
        }
    }
    __syncthreads();
    float w0[25], w1[25];
#pragma unroll
    for (int i = 0; i < 25; i++) {
        w0[i] = wgt[(2 * cp) * 25 + i];
        w1[i] = wgt[(2 * cp + 1) * 25 + i];
    }
    __half* oC0 = out + ((size_t)b * 384 + 2 * cp) * HW;
    __half* oC1 = oC0 + HW;
#pragma unroll
    for (int p = 0; p < 4; p++) {
        int px = tid + p * 256;
        int ry = px >> 7, x = px & 127;
        float a0 = 0.f, a1 = 0.f;
#pragma unroll
        for (int r = 0; r < 5; r++)
#pragma unroll
            for (int s = 0; s < 5; s++) {
                a0 += w0[r * 5 + s] * sh[0][ry + r][x + s];
                a1 += w1[r * 5 + s] * sh[1][ry + r][x + s];
            }
        oC0[(y0 + ry) * WW + x] = __float2half(a0);
        oC1[(y0 + ry) * WW + x] = __float2half(a1);
    }
}

// ---------------- grouped 1x1, 8->8 per group, 2 pixels/thread (half2 io) ----------------
__global__ void pw_group_k(const uint32_t* __restrict__ in, const float* __restrict__ wgt,
                           uint32_t* __restrict__ out) {
    __shared__ float wsh[64];
    int g = blockIdx.y;
    int b = blockIdx.z;
    if (threadIdx.x < 64) wsh[threadIdx.x] = wgt[g * 64 + threadIdx.x];
    __syncthreads();
    int n2 = blockIdx.x * 256 + threadIdx.x;
    const uint32_t* ip = in + ((size_t)b * 384 + g * 8) * (HW / 2) + n2;
    float2 xi[8];
#pragma unroll
    for (int i = 0; i < 8; i++) {
        __half2 h = *(const __half2*)&ip[(size_t)i * (HW / 2)];
        xi[i] = __half22float2(h);
    }
    uint32_t* op = out + ((size_t)b * 768 + 384 + g * 8) * (HW / 2) + n2;
#pragma unroll
    for (int o = 0; o < 8; o++) {
        float a0 = 0.f, a1 = 0.f;
#pragma unroll
        for (int i = 0; i < 8; i++) {
            a0 += wsh[o * 8 + i] * xi[i].x;
            a1 += wsh[o * 8 + i] * xi[i].y;
        }
        op[(size_t)o * (HW / 2)] = packh2(a0, a1);
    }
}

// ---------------- attention phase 1: partial kv per chunk (no atomics) ----------------
__global__ void attn_kv_k(const __half* __restrict__ multi, float* __restrict__ kv) {
    int b = blockIdx.z, g = blockIdx.y;
    int chunk = blockIdx.x;
    const __half* base = multi + ((size_t)b * 768 + g * 24) * HW;
    int n0 = chunk * 8192;
    float acc[72];
#pragma unroll
    for (int i = 0; i < 72; i++) acc[i] = 0.f;
    for (int n = n0 + 2 * threadIdx.x; n < n0 + 8192; n += 512) {
        float2 kq[8], vv[8];
#pragma unroll
        for (int j = 0; j < 8; j++) {
            __half2 h = *(const __half2*)&base[(size_t)(8 + j) * HW + n];
            float2 f = __half22float2(h);
            kq[j].x = fmaxf(f.x, 0.f);
            kq[j].y = fmaxf(f.y, 0.f);
        }
#pragma unroll
        for (int e = 0; e < 8; e++) {
            __half2 h = *(const __half2*)&base[(size_t)(16 + e) * HW + n];
            vv[e] = __half22float2(h);
        }
#pragma unroll
        for (int e = 0; e < 8; e++)
#pragma unroll
            for (int j = 0; j < 8; j++)
                acc[e * 8 + j] += vv[e].x * kq[j].x + vv[e].y * kq[j].y;
#pragma unroll
        for (int j = 0; j < 8; j++) acc[64 + j] += kq[j].x + kq[j].y;
    }
    __shared__ float red[72][8];
    int lane = threadIdx.x & 31, warp = threadIdx.x >> 5;
#pragma unroll
    for (int i = 0; i < 72; i++) {
        float v = acc[i];
        v += __shfl_down_sync(0xffffffffu, v, 16);
        v += __shfl_down_sync(0xffffffffu, v, 8);
        v += __shfl_down_sync(0xffffffffu, v, 4);
        v += __shfl_down_sync(0xffffffffu, v, 2);
        v += __shfl_down_sync(0xffffffffu, v, 1);
        if (lane == 0) red[i][warp] = v;
    }
    __syncthreads();
    if (threadIdx.x < 72) {
        float s = 0.f;
#pragma unroll
        for (int w = 0; w < 8; w++) s += red[threadIdx.x][w];
        kv[(((size_t)b * 32 + g) * 2 + chunk) * 72 + threadIdx.x] = s;
    }
}

// ---------------- attention phase 2: 2 pixels/thread, half2-pair out ----------------
__global__ void attn_apply_k(const __half* __restrict__ multi, const float* __restrict__ kv,
                             uint32_t* __restrict__ attI) {
    int b = blockIdx.z, g = blockIdx.y;
    __shared__ float kvs[72];
    if (threadIdx.x < 72) {
        const float* kvp = kv + ((size_t)b * 32 + g) * 2 * 72 + threadIdx.x;
        kvs[threadIdx.x] = kvp[0] + kvp[72];
    }
    __syncthreads();
    int n = (blockIdx.x * 256 + threadIdx.x) * 2;
    const __half* base = multi + ((size_t)b * 768 + g * 24) * HW + n;
    float2 q[8];
#pragma unroll
    for (int j = 0; j < 8; j++) {
        __half2 h = *(const __half2*)&base[(size_t)j * HW];
        float2 f = __half22float2(h);
        q[j].x = fmaxf(f.x, 0.f);
        q[j].y = fmaxf(f.y, 0.f);
    }
    float d0 = 0.f, d1 = 0.f;
#pragma unroll
    for (int j = 0; j < 8; j++) {
        d0 += kvs[64 + j] * q[j].x;
        d1 += kvs[64 + j] * q[j].y;
    }
    float inv0 = 1.f / (d0 + 1e-15f);
    float inv1 = 1.f / (d1 + 1e-15f);
    uint32_t* op = attI + ((size_t)b * 128 + g * 4) * HW + n;
#pragma unroll
    for (int e2 = 0; e2 < 4; e2++) {
        float sa0 = 0.f, sb0 = 0.f, sa1 = 0.f, sb1 = 0.f;
#pragma unroll
        for (int j = 0; j < 8; j++) {
            float ka = kvs[(2 * e2) * 8 + j], kb = kvs[(2 * e2 + 1) * 8 + j];
            sa0 += ka * q[j].x;
            sb0 += kb * q[j].x;
            sa1 += ka * q[j].y;
            sb1 += kb * q[j].y;
        }
        uint2 o;
        o.x = packh2(sa0 * inv0, sb0 * inv0);
        o.y = packh2(sa1 * inv1, sb1 * inv1);
        *(uint2*)&op[(size_t)e2 * HW] = o;
    }
}

// ---------------- 3x3 dw + bias + hswish, channel PAIR per block, half2 out ----------------
__global__ void dw3x3_k(const __half* __restrict__ in, const float* __restrict__ wgt,
                        const float* __restrict__ bias, uint32_t* __restrict__ outI) {
    __shared__ float sh[2][10][136];
    int tid = threadIdx.x;
    int warp = tid >> 5, lane = tid & 31;
    int y0 = blockIdx.x * 8;
    int cp = blockIdx.y;
    int b = blockIdx.z;
    const __half* inC = in + ((size_t)b * 768 + 2 * cp) * HW;
    for (int rr = warp; rr < 20; rr += 8) {
        int ch = rr / 10, row = rr % 10;
        int yy = y0 - 1 + row;
        const __half* ip = inC + (size_t)ch * HW;
        for (int col = lane; col < 130; col += 32) {
            int xx = col - 1;
            float v = 0.f;
            if (yy >= 0 && yy < HH && xx >= 0 && xx < WW) v = __half2float(ip[yy * WW + xx]);
            sh[ch][row][col] = v;
        }
    }
    __syncthreads();
    float w0[9], w1[9];
#pragma unroll
    for (int i = 0; i < 9; i++) {
        w0[i] = wgt[(2 * cp) * 9 + i];
        w1[i] = wgt[(2 * cp + 1) * 9 + i];
    }
    float bv0 = bias[2 * cp], bv1 = bias[2 * cp + 1];
    uint32_t* oC = outI + ((size_t)b * 384 + cp) * HW;
#pragma unroll
    for (int p = 0; p < 4; p++) {
        int px = tid + p * 256;
        int ry = px >> 7, x = px & 127;
        float a0 = bv0, a1 = bv1;
#pragma unroll
        for (int r = 0; r < 3; r++)
#pragma unroll
            for (int s = 0; s < 3; s++) {
                a0 += w0[r * 3 + s] * sh[0][ry + r][x + s];
                a1 += w1[r * 3 + s] * sh[1][ry + r][x + s];
            }
        oC[(y0 + ry) * WW + x] = packh2(hswish_f(a0), hswish_f(a1));
    }
}

// ---------------- launch ----------------
extern "C" void kernel_launch(void* const* d_in, const int* in_sizes, int n_in,
                              void* d_out, int out_size) {
    const float* ref = (const float*)d_in[0];
    const float* oth = (const float*)d_in[1];
    const float* wq = (const float*)d_in[2];
    const float* bq = (const float*)d_in[3];
    const float* wk = (const float*)d_in[4];
    const float* bk = (const float*)d_in[5];
    const float* wv = (const float*)d_in[6];
    const float* bv = (const float*)d_in[7];
    const float* agg_dw_w = (const float*)d_in[8];
    const float* agg_pw_w = (const float*)d_in[9];
    const float* attn_proj_w = (const float*)d_in[10];
    const float* bn1_g = (const float*)d_in[11];
    const float* bn1_b = (const float*)d_in[12];
    const float* bn1_m = (const float*)d_in[13];
    const float* bn1_v = (const float*)d_in[14];
    const float* mb1_w = (const float*)d_in[15];
    const float* mb1_b = (const float*)d_in[16];
    const float* mb2_w = (const float*)d_in[17];
    const float* mb2_b = (const float*)d_in[18];
    const float* mb3_w = (const float*)d_in[19];
    const float* bn2_g = (const float*)d_in[20];
    const float* bn2_b = (const float*)d_in[21];
    const float* bn2_m = (const float*)d_in[22];
    const float* bn2_v = (const float*)d_in[23];

    __half *multi, *msdw, *h1;
    uint32_t *atti, *h2i, *refi, *othi;
    float *attended, *kv, *wT;
    cudaGetSymbolAddress((void**)&multi, g_multi);
    cudaGetSymbolAddress((void**)&msdw, g_msdw);
    cudaGetSymbolAddress((void**)&atti, g_atti);
    cudaGetSymbolAddress((void**)&attended, g_attended);
    cudaGetSymbolAddress((void**)&h1, g_h1);
    cudaGetSymbolAddress((void**)&h2i, g_h2i);
    cudaGetSymbolAddress((void**)&kv, g_kv);
    cudaGetSymbolAddress((void**)&wT, g_wT);
    cudaGetSymbolAddress((void**)&refi, g_refi);
    cudaGetSymbolAddress((void**)&othi, g_othi);
    uint4* fr4 = (uint4*)wT;

    static bool attr_set = false;
    if (!attr_set) {
        cudaFuncSetAttribute(conv3x3_tc, cudaFuncAttributeMaxDynamicSharedMemorySize,
                             CONV_SMEM);
        attr_set = true;
    }

    // prep: interleave inputs + weight fragment packing
    prep_interleave<<<BB * 64 * HW / 256, 256>>>(ref, oth, refi, othi);
    prep_conv_frag_h3<<<dim3(72, 3), 256>>>(wq, wk, wv, fr4 + FQ);
    prep_gemm_frag_h<<<16, 256>>>(attn_proj_w, fr4 + FP, 256, 128);
    prep_gemm_frag_h<<<48, 256>>>(mb1_w, fr4 + F1, 128, 768);
    prep_gemm_frag_h<<<48, 256>>>(mb3_w, fr4 + F3, 768, 128);

    // fused q,k,v 3x3 convs (M=128/block, pipelined) -> multi channels 0/128/256
    conv3x3_tc<<<dim3(128, 3, 4), 256, CONV_SMEM>>>(refi, othi, fr4 + FQ, bq, bk, bv, multi);

    // aggregation: 5x5 dw (channel pair, 8 rows/block) then grouped 1x1
    dw5x5_k<<<dim3(16, 192, 4), 256>>>(multi, agg_dw_w, msdw);
    pw_group_k<<<dim3(32, 48, 4), 256>>>((const uint32_t*)msdw, agg_pw_w, (uint32_t*)multi);

    // relu linear attention (fp16 io, fp32 accum, partial-kv no atomics)
    attn_kv_k<<<dim3(2, 32, 4), 256>>>(multi, kv);
    attn_apply_k<<<dim3(32, 32, 4), 256>>>(multi, kv, atti);

    // attn_proj + bn1 + residual(ref fp32) -> attended (fp32)
    gemm1x1_tc<1, 2, float><<<dim3(128, 1, 4), 256>>>(
        atti, 256, fr4 + FP, 128, bn1_g, bn1_b, bn1_m, bn1_v, ref, attended);

    // MBConv
    gemm1x1_tc<0, 0, __half><<<dim3(128, 6, 4), 256>>>(
        attended, 128, fr4 + F1, 768, mb1_b, nullptr, nullptr, nullptr, nullptr, h1);
    dw3x3_k<<<dim3(16, 384, 4), 256>>>(h1, mb2_w, mb2_b, h2i);
    gemm1x1_tc<1, 2, float><<<dim3(128, 1, 4), 256>>>(
        h2i, 768, fr4 + F3, 128, bn2_g, bn2_b, bn2_m, bn2_v, attended, (float*)d_out);
}